// round 12
// baseline (speedup 1.0000x reference)
#include <cuda_runtime.h>
#include <cuda_bf16.h>
#include <math_constants.h>
#include <cstdint>

// Problem constants
#define BB 4
#define LL 8192
#define DD 768
#define MAXS 100
#define GM (BB*MAXS)   // 400
#define M2 512         // padded M storage (rows 400-511 zero)
#define GN DD          // 768
#define GK DD          // 768
#define NK16 (GK/16)   // 48
#define MTC 28         // computed m-tiles (448 rows >= 400)
#define NT (GN/8)      // 96 n-tiles

// pool config
#define TCH 32
#define PBLK 192
#define POOL_BLOCKS ((LL/TCH)*BB)        // 1024

// convert sizes
#define A16 (NK16 * MTC * 32)   // 43008
#define B16 (NK16 * NT * 32)    // 147456
#define CVB_BLOCKS (B16 / PBLK) // 768

// gemm config
#define SPLITK 12
#define K16_PER_Z (NK16/SPLITK) // 4 stages per block
#define GEMM_THREADS 128

// Scratch (device globals; allocation is forbidden)
__device__ float g_pooled[M2 * GK];        // [512][768] pooled, m-major
__device__ uint4 g_afb[A16];               // A frags big   [k16][mt][t]
__device__ uint4 g_afs[A16];               // A frags small
__device__ uint2 g_bfb[B16];               // B frags big   [k16][nt][t]
__device__ uint2 g_bfs[B16];               // B frags small
__device__ float g_part[SPLITK][M2 * GN];  // split-K partials

// ---------------------------------------------------------------------------
// helpers
// ---------------------------------------------------------------------------
__device__ __forceinline__ void atomMaxF(float* a, float v) {
    if (v >= 0.0f) atomicMax((int*)a, __float_as_int(v));
    else           atomicMin((unsigned int*)a, __float_as_uint(v));
}
__device__ __forceinline__ void cp_async16(unsigned int smem, const void* gmem) {
    asm volatile("cp.async.cg.shared.global [%0], [%1], 16;\n" :: "r"(smem), "l"(gmem));
}
__device__ __forceinline__ void cp_commit() {
    asm volatile("cp.async.commit_group;\n");
}
template <int N>
__device__ __forceinline__ void cp_wait() {
    asm volatile("cp.async.wait_group %0;\n" :: "n"(N));
}
__device__ __forceinline__ void bsplit(float x, __nv_bfloat16& b, __nv_bfloat16& s) {
    b = __float2bfloat16(x);
    float r = isinf(x) ? 0.0f : x - __bfloat162float(b);
    s = __float2bfloat16(r);
}
__device__ __forceinline__ unsigned packb(__nv_bfloat16 lo, __nv_bfloat16 hi) {
    __nv_bfloat162 v; v.x = lo; v.y = hi;
    return *reinterpret_cast<unsigned*>(&v);
}
__device__ __forceinline__ void mma_bf16(float4& d, uint4 a, uint2 b) {
    asm("mma.sync.aligned.m16n8k16.row.col.f32.bf16.bf16.f32 "
        "{%0,%1,%2,%3}, {%4,%5,%6,%7}, {%8,%9}, {%0,%1,%2,%3};"
        : "+f"(d.x), "+f"(d.y), "+f"(d.z), "+f"(d.w)
        : "r"(a.x), "r"(a.y), "r"(a.z), "r"(a.w), "r"(b.x), "r"(b.y));
}

// ---------------------------------------------------------------------------
// Init: g_pooled rows <400: -inf on valid slots else 0; rows 400-511: 0.
// ---------------------------------------------------------------------------
__global__ __launch_bounds__(256) void init_kernel(const int* __restrict__ ids) {
    int i4 = blockIdx.x * 256 + threadIdx.x;       // 0..98303
    int m = (i4 * 4) / DD;
    float val = 0.0f;
    if (m < GM) {
        int b = m / MAXS;
        int s = m - b * MAXS;
        int bbmax = __ldg(&ids[b * LL + LL - 1]);
        val = (s < bbmax) ? -CUDART_INF_F : 0.0f;
    }
    ((float4*)g_pooled)[i4] = make_float4(val, val, val, val);
}

// ---------------------------------------------------------------------------
// Pool + convert-B fused (independent jobs, overlap in one launch).
// ---------------------------------------------------------------------------
__global__ __launch_bounds__(PBLK) void pool_kernel(const float* __restrict__ wf,
                                                    const int* __restrict__ ids,
                                                    const float* __restrict__ W2) {
    __shared__ int sid[TCH];
    const int tid = threadIdx.x;

    if (blockIdx.x < CVB_BLOCKS) {
        int j = blockIdx.x * PBLK + tid;           // 0..B16-1
        int t  = j & 31;
        int nt = (j >> 5) % NT;
        int k16 = j / (NT * 32);
        int g = t >> 2, c = (t & 3) * 2;
        int n  = nt * 8 + g;
        int k0 = k16 * 16 + c;
        const float* __restrict__ row = W2 + (size_t)n * GK;
        __nv_bfloat16 b00, s00, b01, s01, b10, s10, b11, s11;
        bsplit(row[k0],     b00, s00);
        bsplit(row[k0 + 1], b01, s01);
        bsplit(row[k0 + 8], b10, s10);
        bsplit(row[k0 + 9], b11, s11);
        g_bfb[j] = make_uint2(packb(b00, b01), packb(b10, b11));
        g_bfs[j] = make_uint2(packb(s00, s01), packb(s10, s11));
        return;
    }

    const int pb = blockIdx.x - CVB_BLOCKS;
    const int b = pb >> 8;                   // 256 chunks per batch
    const int c0 = (pb & 255) * TCH;
    if (tid < TCH) sid[tid] = ids[b * LL + c0 + tid];
    __syncthreads();

    const float4* __restrict__ base =
        (const float4*)(wf + ((size_t)b * LL + c0) * DD) + tid;

    float4 run = make_float4(-CUDART_INF_F, -CUDART_INF_F, -CUDART_INF_F, -CUDART_INF_F);
    int cur = -1;
    const int d0 = tid * 4;

#pragma unroll
    for (int t0 = 0; t0 < TCH; t0 += 8) {
        float4 v[8];
#pragma unroll
        for (int j = 0; j < 8; ++j)
            v[j] = __ldcs(base + (size_t)(t0 + j) * (DD / 4));
#pragma unroll
        for (int j = 0; j < 8; ++j) {
            int id = sid[t0 + j];
            if (id != cur) {
                if (cur > 0) {
                    float* p = g_pooled + (size_t)(b * MAXS + cur - 1) * DD + d0;
                    atomMaxF(p + 0, run.x);
                    atomMaxF(p + 1, run.y);
                    atomMaxF(p + 2, run.z);
                    atomMaxF(p + 3, run.w);
                }
                cur = id;
                run = make_float4(-CUDART_INF_F, -CUDART_INF_F, -CUDART_INF_F, -CUDART_INF_F);
            }
            if (id > 0) {
                run.x = fmaxf(run.x, v[j].x);
                run.y = fmaxf(run.y, v[j].y);
                run.z = fmaxf(run.z, v[j].z);
                run.w = fmaxf(run.w, v[j].w);
            }
        }
    }
    if (cur > 0) {
        float* p = g_pooled + (size_t)(b * MAXS + cur - 1) * DD + d0;
        atomMaxF(p + 0, run.x);
        atomMaxF(p + 1, run.y);
        atomMaxF(p + 2, run.z);
        atomMaxF(p + 3, run.w);
    }
}

// ---------------------------------------------------------------------------
// Convert-A: pooled -> bf16 big/small fragments (m16n8k16 A layout).
// ---------------------------------------------------------------------------
__global__ __launch_bounds__(256) void convertA_kernel() {
    int i = blockIdx.x * 256 + threadIdx.x;
    if (i >= A16) return;
    int t  = i & 31;
    int rest = i >> 5;
    int mt = rest % MTC;
    int k16 = rest / MTC;
    int g = t >> 2, c = (t & 3) * 2;
    int r0 = mt * 16 + g, r1 = r0 + 8;
    int k0 = k16 * 16 + c;
    const float* __restrict__ row0 = g_pooled + (size_t)r0 * GK;
    const float* __restrict__ row1 = g_pooled + (size_t)r1 * GK;
    __nv_bfloat16 bb[8], ss[8];
    bsplit(row0[k0],     bb[0], ss[0]);
    bsplit(row0[k0 + 1], bb[1], ss[1]);
    bsplit(row1[k0],     bb[2], ss[2]);
    bsplit(row1[k0 + 1], bb[3], ss[3]);
    bsplit(row0[k0 + 8], bb[4], ss[4]);
    bsplit(row0[k0 + 9], bb[5], ss[5]);
    bsplit(row1[k0 + 8], bb[6], ss[6]);
    bsplit(row1[k0 + 9], bb[7], ss[7]);
    int idx = (k16 * MTC + mt) * 32 + t;
    g_afb[idx] = make_uint4(packb(bb[0], bb[1]), packb(bb[2], bb[3]),
                            packb(bb[4], bb[5]), packb(bb[6], bb[7]));
    g_afs[idx] = make_uint4(packb(ss[0], ss[1]), packb(ss[2], ss[3]),
                            packb(ss[4], ss[5]), packb(ss[6], ss[7]));
}

// ---------------------------------------------------------------------------
// GEMM (3xBF16 m16n8k16): grid (7, 12, 12) = 1008 blocks, 128 thr = 4 warps.
// Block tile 64m x 64n; warp tile 32m x 32n (2 mt x 4 nt, 24 mma/stage).
// 4 stages per block; 4-deep cp.async pipeline, wait_group<2>.
// ---------------------------------------------------------------------------
__global__ __launch_bounds__(GEMM_THREADS) void gemm_kernel() {
    __shared__ uint4 sA[4][2][128];   // [buf][big/sm][mt_local*32+t] 16KB
    __shared__ uint2 sB[4][2][256];   // [buf][big/sm][nt_local*32+t] 16KB

    const int mb4 = blockIdx.x * 4;        // mtile base (0..24)
    const int nb8 = blockIdx.y * 8;        // ntile base
    const int z = blockIdx.z;
    const int k16z = z * K16_PER_Z;

    const int tid = threadIdx.x;
    const int lane = tid & 31;
    const int wid = tid >> 5;
    const int mwarp = wid >> 1;            // 0..1
    const int nwarp = wid & 1;             // 0..1

    auto load_stage = [&](int st) {
        if (st < K16_PER_Z) {
            const int buf = st & 3;
            const int k16g = k16z + st;
            const uint4* srcAb = g_afb + ((size_t)k16g * MTC + mb4) * 32;
            const uint4* srcAs = g_afs + ((size_t)k16g * MTC + mb4) * 32;
            const uint4* srcBb = (const uint4*)(g_bfb + ((size_t)k16g * NT + nb8) * 32);
            const uint4* srcBs = (const uint4*)(g_bfs + ((size_t)k16g * NT + nb8) * 32);
            cp_async16((unsigned int)__cvta_generic_to_shared(&sA[buf][0][tid]), srcAb + tid);
            cp_async16((unsigned int)__cvta_generic_to_shared(&sA[buf][1][tid]), srcAs + tid);
            cp_async16((unsigned int)__cvta_generic_to_shared(&sB[buf][0][2 * tid]), srcBb + tid);
            cp_async16((unsigned int)__cvta_generic_to_shared(&sB[buf][1][2 * tid]), srcBs + tid);
        }
        cp_commit();
    };

    float4 acc[2][4];
#pragma unroll
    for (int i = 0; i < 2; ++i)
#pragma unroll
        for (int j = 0; j < 4; ++j) acc[i][j] = make_float4(0.f, 0.f, 0.f, 0.f);

    load_stage(0);
    load_stage(1);
    load_stage(2);

#pragma unroll
    for (int st = 0; st < K16_PER_Z; ++st) {
        cp_wait<2>();
        __syncthreads();

        load_stage(st + 3);

        const int buf = st & 3;
        uint4 ab[2], as_[2];
        uint2 bbv[4], bsv[4];
#pragma unroll
        for (int i = 0; i < 2; ++i) {
            int mtl = mwarp * 2 + i;
            ab[i]  = sA[buf][0][mtl * 32 + lane];
            as_[i] = sA[buf][1][mtl * 32 + lane];
        }
#pragma unroll
        for (int j = 0; j < 4; ++j) {
            int ntl = nwarp * 4 + j;
            bbv[j] = sB[buf][0][ntl * 32 + lane];
            bsv[j] = sB[buf][1][ntl * 32 + lane];
        }
#pragma unroll
        for (int i = 0; i < 2; ++i)
#pragma unroll
            for (int j = 0; j < 4; ++j) {
                mma_bf16(acc[i][j], ab[i], bbv[j]);    // big*big
                mma_bf16(acc[i][j], ab[i], bsv[j]);    // big*small
                mma_bf16(acc[i][j], as_[i], bbv[j]);   // small*big
            }
    }

    // epilogue
    float* __restrict__ part = g_part[z];
    const int g = lane >> 2;
    const int c2 = (lane & 3) * 2;
#pragma unroll
    for (int i = 0; i < 2; ++i) {
#pragma unroll
        for (int j = 0; j < 4; ++j) {
            int m0 = (mb4 + mwarp * 2 + i) * 16 + g;
            int n0 = (nb8 + nwarp * 4 + j) * 8 + c2;
            *(float2*)&part[(size_t)m0 * GN + n0] = make_float2(acc[i][j].x, acc[i][j].y);
            *(float2*)&part[(size_t)(m0 + 8) * GN + n0] = make_float2(acc[i][j].z, acc[i][j].w);
        }
    }
}

// ---------------------------------------------------------------------------
// Combine split-K partials + bias. 600 blocks x 128 thr, 1 float4 each.
// ---------------------------------------------------------------------------
__global__ __launch_bounds__(128) void combine_kernel(const float* __restrict__ b2,
                                                      float* __restrict__ out) {
    int i = blockIdx.x * 128 + threadIdx.x;       // over GM*GN/4 = 76800
    float4 r = ((const float4*)b2)[i % (GN / 4)];
#pragma unroll
    for (int z = 0; z < SPLITK; ++z) {
        float4 p = ((const float4*)g_part[z])[i];
        r.x += p.x; r.y += p.y; r.z += p.z; r.w += p.w;
    }
    ((float4*)out)[i] = r;
}

// ---------------------------------------------------------------------------
extern "C" void kernel_launch(void* const* d_in, const int* in_sizes, int n_in,
                              void* d_out, int out_size) {
    const float* wf  = (const float*)d_in[0];   // [4,8192,768] f32
    const int*   ids = (const int*)d_in[1];     // [4,8192] i32
    const float* W2  = (const float*)d_in[2];   // [768,768] f32
    const float* b2  = (const float*)d_in[3];   // [768] f32
    float* out = (float*)d_out;                 // [4,100,768] f32

    init_kernel<<<384, 256>>>(ids);
    pool_kernel<<<CVB_BLOCKS + POOL_BLOCKS, PBLK>>>(wf, ids, W2);
    convertA_kernel<<<(A16 + 255) / 256, 256>>>();
    gemm_kernel<<<dim3(7, GN / 64, SPLITK), GEMM_THREADS>>>();
    combine_kernel<<<600, 128>>>(b2, out);
}

// round 14
// speedup vs baseline: 1.1298x; 1.1298x over previous
#include <cuda_runtime.h>
#include <cuda_bf16.h>
#include <math_constants.h>
#include <cstdint>

// Problem constants
#define BB 4
#define LL 8192
#define DD 768
#define MAXS 100
#define GM (BB*MAXS)   // 400
#define M2 512         // padded M storage (rows 400-511 zero)
#define GN DD          // 768
#define GK DD          // 768
#define NK16 (GK/16)   // 48
#define MTC 28         // computed m-tiles (448 rows >= 400)
#define MTV 25         // valid m-tiles (400 rows)
#define NT (GN/8)      // 96 n-tiles

// pool config
#define TCH 32
#define PBLK 192
#define POOL_BLOCKS ((LL/TCH)*BB)        // 1024

// convert sizes
#define A16 (NK16 * MTC * 32)   // 43008
#define B16 (NK16 * NT * 32)    // 147456
#define CVB_BLOCKS (B16 / PBLK) // 768

// gemm config (R10-winning shape)
#define SPLITK 6
#define K16_PER_Z (NK16/SPLITK) // 8 stages per block
#define GEMM_THREADS 128

// init kernel split
#define INITP_BLOCKS 384        // g_pooled init (98304 float4)
#define BIAS_BLOCKS 300         // out = bias   (76800 float4)

// Scratch (device globals; allocation is forbidden)
__device__ float g_pooled[M2 * GK];        // [512][768] pooled, m-major
__device__ uint4 g_afb[A16];               // A frags big   [k16][mt][t]
__device__ uint4 g_afs[A16];               // A frags small
__device__ uint2 g_bfb[B16];               // B frags big   [k16][nt][t]
__device__ uint2 g_bfs[B16];               // B frags small

// ---------------------------------------------------------------------------
// helpers
// ---------------------------------------------------------------------------
__device__ __forceinline__ void atomMaxF(float* a, float v) {
    if (v >= 0.0f) atomicMax((int*)a, __float_as_int(v));
    else           atomicMin((unsigned int*)a, __float_as_uint(v));
}
__device__ __forceinline__ void cp_async16(unsigned int smem, const void* gmem) {
    asm volatile("cp.async.cg.shared.global [%0], [%1], 16;\n" :: "r"(smem), "l"(gmem));
}
__device__ __forceinline__ void cp_commit() {
    asm volatile("cp.async.commit_group;\n");
}
template <int N>
__device__ __forceinline__ void cp_wait() {
    asm volatile("cp.async.wait_group %0;\n" :: "n"(N));
}
__device__ __forceinline__ void bsplit(float x, __nv_bfloat16& b, __nv_bfloat16& s) {
    b = __float2bfloat16(x);
    float r = isinf(x) ? 0.0f : x - __bfloat162float(b);
    s = __float2bfloat16(r);
}
__device__ __forceinline__ unsigned packb(__nv_bfloat16 lo, __nv_bfloat16 hi) {
    __nv_bfloat162 v; v.x = lo; v.y = hi;
    return *reinterpret_cast<unsigned*>(&v);
}
__device__ __forceinline__ void mma_bf16(float4& d, uint4 a, uint2 b) {
    asm("mma.sync.aligned.m16n8k16.row.col.f32.bf16.bf16.f32 "
        "{%0,%1,%2,%3}, {%4,%5,%6,%7}, {%8,%9}, {%0,%1,%2,%3};"
        : "+f"(d.x), "+f"(d.y), "+f"(d.z), "+f"(d.w)
        : "r"(a.x), "r"(a.y), "r"(a.z), "r"(a.w), "r"(b.x), "r"(b.y));
}
__device__ __forceinline__ void redAdd(float* a, float v) {
    asm volatile("red.global.add.f32 [%0], %1;" :: "l"(a), "f"(v) : "memory");
}

// ---------------------------------------------------------------------------
// Init: blocks [0,384): g_pooled rows <400: -inf on valid slots else 0,
// rows 400-511: 0.  Blocks [384,684): out = bias (replay-safe re-init).
// ---------------------------------------------------------------------------
__global__ __launch_bounds__(256) void init_kernel(const int* __restrict__ ids,
                                                   const float* __restrict__ b2,
                                                   float* __restrict__ out) {
    if (blockIdx.x < INITP_BLOCKS) {
        int i4 = blockIdx.x * 256 + threadIdx.x;       // 0..98303
        int m = (i4 * 4) / DD;
        float val = 0.0f;
        if (m < GM) {
            int b = m / MAXS;
            int s = m - b * MAXS;
            int bbmax = __ldg(&ids[b * LL + LL - 1]);
            val = (s < bbmax) ? -CUDART_INF_F : 0.0f;
        }
        ((float4*)g_pooled)[i4] = make_float4(val, val, val, val);
    } else {
        int i4 = (blockIdx.x - INITP_BLOCKS) * 256 + threadIdx.x;  // 0..76799
        ((float4*)out)[i4] = ((const float4*)b2)[i4 % (GN / 4)];
    }
}

// ---------------------------------------------------------------------------
// Pool + convert-B fused (independent jobs, overlap in one launch).
// ---------------------------------------------------------------------------
__global__ __launch_bounds__(PBLK) void pool_kernel(const float* __restrict__ wf,
                                                    const int* __restrict__ ids,
                                                    const float* __restrict__ W2) {
    __shared__ int sid[TCH];
    const int tid = threadIdx.x;

    if (blockIdx.x < CVB_BLOCKS) {
        int j = blockIdx.x * PBLK + tid;           // 0..B16-1
        int t  = j & 31;
        int nt = (j >> 5) % NT;
        int k16 = j / (NT * 32);
        int g = t >> 2, c = (t & 3) * 2;
        int n  = nt * 8 + g;
        int k0 = k16 * 16 + c;
        const float* __restrict__ row = W2 + (size_t)n * GK;
        __nv_bfloat16 b00, s00, b01, s01, b10, s10, b11, s11;
        bsplit(row[k0],     b00, s00);
        bsplit(row[k0 + 1], b01, s01);
        bsplit(row[k0 + 8], b10, s10);
        bsplit(row[k0 + 9], b11, s11);
        g_bfb[j] = make_uint2(packb(b00, b01), packb(b10, b11));
        g_bfs[j] = make_uint2(packb(s00, s01), packb(s10, s11));
        return;
    }

    const int pb = blockIdx.x - CVB_BLOCKS;
    const int b = pb >> 8;                   // 256 chunks per batch
    const int c0 = (pb & 255) * TCH;
    if (tid < TCH) sid[tid] = ids[b * LL + c0 + tid];
    __syncthreads();

    const float4* __restrict__ base =
        (const float4*)(wf + ((size_t)b * LL + c0) * DD) + tid;

    float4 run = make_float4(-CUDART_INF_F, -CUDART_INF_F, -CUDART_INF_F, -CUDART_INF_F);
    int cur = -1;
    const int d0 = tid * 4;

#pragma unroll
    for (int t0 = 0; t0 < TCH; t0 += 8) {
        float4 v[8];
#pragma unroll
        for (int j = 0; j < 8; ++j)
            v[j] = __ldcs(base + (size_t)(t0 + j) * (DD / 4));
#pragma unroll
        for (int j = 0; j < 8; ++j) {
            int id = sid[t0 + j];
            if (id != cur) {
                if (cur > 0) {
                    float* p = g_pooled + (size_t)(b * MAXS + cur - 1) * DD + d0;
                    atomMaxF(p + 0, run.x);
                    atomMaxF(p + 1, run.y);
                    atomMaxF(p + 2, run.z);
                    atomMaxF(p + 3, run.w);
                }
                cur = id;
                run = make_float4(-CUDART_INF_F, -CUDART_INF_F, -CUDART_INF_F, -CUDART_INF_F);
            }
            if (id > 0) {
                run.x = fmaxf(run.x, v[j].x);
                run.y = fmaxf(run.y, v[j].y);
                run.z = fmaxf(run.z, v[j].z);
                run.w = fmaxf(run.w, v[j].w);
            }
        }
    }
    if (cur > 0) {
        float* p = g_pooled + (size_t)(b * MAXS + cur - 1) * DD + d0;
        atomMaxF(p + 0, run.x);
        atomMaxF(p + 1, run.y);
        atomMaxF(p + 2, run.z);
        atomMaxF(p + 3, run.w);
    }
}

// ---------------------------------------------------------------------------
// Convert-A: pooled -> bf16 big/small fragments (m16n8k16 A layout).
// ---------------------------------------------------------------------------
__global__ __launch_bounds__(256) void convertA_kernel() {
    int i = blockIdx.x * 256 + threadIdx.x;
    if (i >= A16) return;
    int t  = i & 31;
    int rest = i >> 5;
    int mt = rest % MTC;
    int k16 = rest / MTC;
    int g = t >> 2, c = (t & 3) * 2;
    int r0 = mt * 16 + g, r1 = r0 + 8;
    int k0 = k16 * 16 + c;
    const float* __restrict__ row0 = g_pooled + (size_t)r0 * GK;
    const float* __restrict__ row1 = g_pooled + (size_t)r1 * GK;
    __nv_bfloat16 bb[8], ss[8];
    bsplit(row0[k0],     bb[0], ss[0]);
    bsplit(row0[k0 + 1], bb[1], ss[1]);
    bsplit(row1[k0],     bb[2], ss[2]);
    bsplit(row1[k0 + 1], bb[3], ss[3]);
    bsplit(row0[k0 + 8], bb[4], ss[4]);
    bsplit(row0[k0 + 9], bb[5], ss[5]);
    bsplit(row1[k0 + 8], bb[6], ss[6]);
    bsplit(row1[k0 + 9], bb[7], ss[7]);
    int idx = (k16 * MTC + mt) * 32 + t;
    g_afb[idx] = make_uint4(packb(bb[0], bb[1]), packb(bb[2], bb[3]),
                            packb(bb[4], bb[5]), packb(bb[6], bb[7]));
    g_afs[idx] = make_uint4(packb(ss[0], ss[1]), packb(ss[2], ss[3]),
                            packb(ss[4], ss[5]), packb(ss[6], ss[7]));
}

// ---------------------------------------------------------------------------
// GEMM (3xBF16 m16n8k16): grid (7, 12, 6) = 504 blocks, 128 thr = 4 warps.
// Block tile 64m x 64n; warp tile 32m x 32n (2 mt x 4 nt, 24 mma/stage).
// 8 stages/block; 4-deep cp.async pipeline, wait_group<2>.
// Epilogue: red.global.add.f32 directly into out (bias pre-written by init).
// ---------------------------------------------------------------------------
__global__ __launch_bounds__(GEMM_THREADS) void gemm_kernel(float* __restrict__ out) {
    __shared__ uint4 sA[4][2][128];   // [buf][big/sm][mt_local*32+t] 16KB
    __shared__ uint2 sB[4][2][256];   // [buf][big/sm][nt_local*32+t] 16KB

    const int mb4 = blockIdx.x * 4;        // mtile base (0..24)
    const int nb8 = blockIdx.y * 8;        // ntile base
    const int z = blockIdx.z;
    const int k16z = z * K16_PER_Z;

    const int tid = threadIdx.x;
    const int lane = tid & 31;
    const int wid = tid >> 5;
    const int mwarp = wid >> 1;            // 0..1
    const int nwarp = wid & 1;             // 0..1

    auto load_stage = [&](int st) {
        if (st < K16_PER_Z) {
            const int buf = st & 3;
            const int k16g = k16z + st;
            const uint4* srcAb = g_afb + ((size_t)k16g * MTC + mb4) * 32;
            const uint4* srcAs = g_afs + ((size_t)k16g * MTC + mb4) * 32;
            const uint4* srcBb = (const uint4*)(g_bfb + ((size_t)k16g * NT + nb8) * 32);
            const uint4* srcBs = (const uint4*)(g_bfs + ((size_t)k16g * NT + nb8) * 32);
            cp_async16((unsigned int)__cvta_generic_to_shared(&sA[buf][0][tid]), srcAb + tid);
            cp_async16((unsigned int)__cvta_generic_to_shared(&sA[buf][1][tid]), srcAs + tid);
            cp_async16((unsigned int)__cvta_generic_to_shared(&sB[buf][0][2 * tid]), srcBb + tid);
            cp_async16((unsigned int)__cvta_generic_to_shared(&sB[buf][1][2 * tid]), srcBs + tid);
        }
        cp_commit();
    };

    float4 acc[2][4];
#pragma unroll
    for (int i = 0; i < 2; ++i)
#pragma unroll
        for (int j = 0; j < 4; ++j) acc[i][j] = make_float4(0.f, 0.f, 0.f, 0.f);

    load_stage(0);
    load_stage(1);
    load_stage(2);

    for (int st = 0; st < K16_PER_Z; ++st) {
        cp_wait<2>();
        __syncthreads();

        load_stage(st + 3);

        const int buf = st & 3;
        uint4 ab[2], as_[2];
        uint2 bbv[4], bsv[4];
#pragma unroll
        for (int i = 0; i < 2; ++i) {
            int mtl = mwarp * 2 + i;
            ab[i]  = sA[buf][0][mtl * 32 + lane];
            as_[i] = sA[buf][1][mtl * 32 + lane];
        }
#pragma unroll
        for (int j = 0; j < 4; ++j) {
            int ntl = nwarp * 4 + j;
            bbv[j] = sB[buf][0][ntl * 32 + lane];
            bsv[j] = sB[buf][1][ntl * 32 + lane];
        }
#pragma unroll
        for (int i = 0; i < 2; ++i)
#pragma unroll
            for (int j = 0; j < 4; ++j) {
                mma_bf16(acc[i][j], ab[i], bbv[j]);    // big*big
                mma_bf16(acc[i][j], ab[i], bsv[j]);    // big*small
                mma_bf16(acc[i][j], as_[i], bbv[j]);   // small*big
            }
    }

    // epilogue: atomic accumulate into out (bias already there)
    const int g = lane >> 2;
    const int c2 = (lane & 3) * 2;
#pragma unroll
    for (int i = 0; i < 2; ++i) {
        const int mtile = mb4 + mwarp * 2 + i;
        if (mtile < MTV) {                 // rows >= 400 are padding
            const int m0 = mtile * 16 + g;
#pragma unroll
            for (int j = 0; j < 4; ++j) {
                int n0 = (nb8 + nwarp * 4 + j) * 8 + c2;
                float* p0 = &out[(size_t)m0 * GN + n0];
                float* p1 = &out[(size_t)(m0 + 8) * GN + n0];
                redAdd(p0 + 0, acc[i][j].x);
                redAdd(p0 + 1, acc[i][j].y);
                redAdd(p1 + 0, acc[i][j].z);
                redAdd(p1 + 1, acc[i][j].w);
            }
        }
    }
}

// ---------------------------------------------------------------------------
extern "C" void kernel_launch(void* const* d_in, const int* in_sizes, int n_in,
                              void* d_out, int out_size) {
    const float* wf  = (const float*)d_in[0];   // [4,8192,768] f32
    const int*   ids = (const int*)d_in[1];     // [4,8192] i32
    const float* W2  = (const float*)d_in[2];   // [768,768] f32
    const float* b2  = (const float*)d_in[3];   // [768] f32
    float* out = (float*)d_out;                 // [4,100,768] f32

    init_kernel<<<INITP_BLOCKS + BIAS_BLOCKS, 256>>>(ids, b2, out);
    pool_kernel<<<CVB_BLOCKS + POOL_BLOCKS, PBLK>>>(wf, ids, W2);
    convertA_kernel<<<(A16 + 255) / 256, 256>>>();
    gemm_kernel<<<dim3(7, GN / 64, SPLITK), GEMM_THREADS>>>(out);
}

// round 15
// speedup vs baseline: 1.1353x; 1.0049x over previous
#include <cuda_runtime.h>
#include <cuda_bf16.h>
#include <math_constants.h>
#include <cstdint>

// Problem constants
#define BB 4
#define LL 8192
#define DD 768
#define MAXS 100
#define GM (BB*MAXS)   // 400
#define M2 512         // padded M storage (rows 400-511 zero)
#define GN DD          // 768
#define GK DD          // 768
#define NK16 (GK/16)   // 48
#define MTC 28         // computed m-tiles (448 rows >= 400)
#define MTV 25         // valid m-tiles (400 rows)
#define NT (GN/8)      // 96 n-tiles

// pool config
#define TCH 32
#define PBLK 192
#define POOL_BLOCKS ((LL/TCH)*BB)        // 1024

// convert sizes
#define A16 (NK16 * MTC * 32)   // 43008
#define B16 (NK16 * NT * 32)    // 147456
#define CVB_BLOCKS (B16 / PBLK) // 768
#define CVA_BLOCKS (A16 / 256)  // 168
#define BIAS_BLOCKS 300         // out = bias (76800 float4)

// gemm config
#define SPLITK 6
#define K16_PER_Z (NK16/SPLITK) // 8 stages per block
#define GEMM_THREADS 128

#define INITP_BLOCKS 384        // g_pooled init (98304 float4)

// Scratch (device globals; allocation is forbidden)
__device__ float g_pooled[M2 * GK];        // [512][768] pooled, m-major
__device__ uint4 g_afb[A16];               // A frags big   [k16][mt][t]
__device__ uint4 g_afs[A16];               // A frags small
__device__ uint2 g_bfb[B16];               // B frags big   [k16][nt][t]
__device__ uint2 g_bfs[B16];               // B frags small

// ---------------------------------------------------------------------------
// helpers
// ---------------------------------------------------------------------------
__device__ __forceinline__ void atomMaxF(float* a, float v) {
    if (v >= 0.0f) atomicMax((int*)a, __float_as_int(v));
    else           atomicMin((unsigned int*)a, __float_as_uint(v));
}
__device__ __forceinline__ void cp_async16(unsigned int smem, const void* gmem) {
    asm volatile("cp.async.cg.shared.global [%0], [%1], 16;\n" :: "r"(smem), "l"(gmem));
}
__device__ __forceinline__ void cp_commit() {
    asm volatile("cp.async.commit_group;\n");
}
template <int N>
__device__ __forceinline__ void cp_wait() {
    asm volatile("cp.async.wait_group %0;\n" :: "n"(N));
}
__device__ __forceinline__ void bsplit(float x, __nv_bfloat16& b, __nv_bfloat16& s) {
    b = __float2bfloat16(x);
    float r = isinf(x) ? 0.0f : x - __bfloat162float(b);
    s = __float2bfloat16(r);
}
__device__ __forceinline__ unsigned packb(__nv_bfloat16 lo, __nv_bfloat16 hi) {
    __nv_bfloat162 v; v.x = lo; v.y = hi;
    return *reinterpret_cast<unsigned*>(&v);
}
__device__ __forceinline__ void mma_bf16(float4& d, uint4 a, uint2 b) {
    asm("mma.sync.aligned.m16n8k16.row.col.f32.bf16.bf16.f32 "
        "{%0,%1,%2,%3}, {%4,%5,%6,%7}, {%8,%9}, {%0,%1,%2,%3};"
        : "+f"(d.x), "+f"(d.y), "+f"(d.z), "+f"(d.w)
        : "r"(a.x), "r"(a.y), "r"(a.z), "r"(a.w), "r"(b.x), "r"(b.y));
}
__device__ __forceinline__ void redAdd(float* a, float v) {
    asm volatile("red.global.add.f32 [%0], %1;" :: "l"(a), "f"(v) : "memory");
}

// ---------------------------------------------------------------------------
// Init: g_pooled rows <400: -inf on valid slots else 0; rows 400-511: 0.
// ---------------------------------------------------------------------------
__global__ __launch_bounds__(256) void init_kernel(const int* __restrict__ ids) {
    int i4 = blockIdx.x * 256 + threadIdx.x;       // 0..98303
    int m = (i4 * 4) / DD;
    float val = 0.0f;
    if (m < GM) {
        int b = m / MAXS;
        int s = m - b * MAXS;
        int bbmax = __ldg(&ids[b * LL + LL - 1]);
        val = (s < bbmax) ? -CUDART_INF_F : 0.0f;
    }
    ((float4*)g_pooled)[i4] = make_float4(val, val, val, val);
}

// ---------------------------------------------------------------------------
// Pool + convert-B fused (independent jobs, overlap in one launch).
// ---------------------------------------------------------------------------
__global__ __launch_bounds__(PBLK) void pool_kernel(const float* __restrict__ wf,
                                                    const int* __restrict__ ids,
                                                    const float* __restrict__ W2) {
    __shared__ int sid[TCH];
    const int tid = threadIdx.x;

    if (blockIdx.x < CVB_BLOCKS) {
        int j = blockIdx.x * PBLK + tid;           // 0..B16-1
        int t  = j & 31;
        int nt = (j >> 5) % NT;
        int k16 = j / (NT * 32);
        int g = t >> 2, c = (t & 3) * 2;
        int n  = nt * 8 + g;
        int k0 = k16 * 16 + c;
        const float* __restrict__ row = W2 + (size_t)n * GK;
        __nv_bfloat16 b00, s00, b01, s01, b10, s10, b11, s11;
        bsplit(row[k0],     b00, s00);
        bsplit(row[k0 + 1], b01, s01);
        bsplit(row[k0 + 8], b10, s10);
        bsplit(row[k0 + 9], b11, s11);
        g_bfb[j] = make_uint2(packb(b00, b01), packb(b10, b11));
        g_bfs[j] = make_uint2(packb(s00, s01), packb(s10, s11));
        return;
    }

    const int pb = blockIdx.x - CVB_BLOCKS;
    const int b = pb >> 8;                   // 256 chunks per batch
    const int c0 = (pb & 255) * TCH;
    if (tid < TCH) sid[tid] = ids[b * LL + c0 + tid];
    __syncthreads();

    const float4* __restrict__ base =
        (const float4*)(wf + ((size_t)b * LL + c0) * DD) + tid;

    float4 run = make_float4(-CUDART_INF_F, -CUDART_INF_F, -CUDART_INF_F, -CUDART_INF_F);
    int cur = -1;
    const int d0 = tid * 4;

#pragma unroll
    for (int t0 = 0; t0 < TCH; t0 += 8) {
        float4 v[8];
#pragma unroll
        for (int j = 0; j < 8; ++j)
            v[j] = __ldcs(base + (size_t)(t0 + j) * (DD / 4));
#pragma unroll
        for (int j = 0; j < 8; ++j) {
            int id = sid[t0 + j];
            if (id != cur) {
                if (cur > 0) {
                    float* p = g_pooled + (size_t)(b * MAXS + cur - 1) * DD + d0;
                    atomMaxF(p + 0, run.x);
                    atomMaxF(p + 1, run.y);
                    atomMaxF(p + 2, run.z);
                    atomMaxF(p + 3, run.w);
                }
                cur = id;
                run = make_float4(-CUDART_INF_F, -CUDART_INF_F, -CUDART_INF_F, -CUDART_INF_F);
            }
            if (id > 0) {
                run.x = fmaxf(run.x, v[j].x);
                run.y = fmaxf(run.y, v[j].y);
                run.z = fmaxf(run.z, v[j].z);
                run.w = fmaxf(run.w, v[j].w);
            }
        }
    }
    if (cur > 0) {
        float* p = g_pooled + (size_t)(b * MAXS + cur - 1) * DD + d0;
        atomMaxF(p + 0, run.x);
        atomMaxF(p + 1, run.y);
        atomMaxF(p + 2, run.z);
        atomMaxF(p + 3, run.w);
    }
}

// ---------------------------------------------------------------------------
// Convert-A + bias-prewrite fused.
// Blocks [0, CVA_BLOCKS): pooled -> bf16 big/small fragments.
// Blocks [CVA_BLOCKS, +BIAS_BLOCKS): out = bias (replay-safe re-init).
// ---------------------------------------------------------------------------
__global__ __launch_bounds__(256) void convertA_kernel(const float* __restrict__ b2,
                                                       float* __restrict__ out) {
    if (blockIdx.x >= CVA_BLOCKS) {
        int i4 = (blockIdx.x - CVA_BLOCKS) * 256 + threadIdx.x;  // 0..76799
        ((float4*)out)[i4] = ((const float4*)b2)[i4 % (GN / 4)];
        return;
    }
    int i = blockIdx.x * 256 + threadIdx.x;        // 0..A16-1 (exact)
    int t  = i & 31;
    int rest = i >> 5;
    int mt = rest % MTC;
    int k16 = rest / MTC;
    int g = t >> 2, c = (t & 3) * 2;
    int r0 = mt * 16 + g, r1 = r0 + 8;
    int k0 = k16 * 16 + c;
    const float* __restrict__ row0 = g_pooled + (size_t)r0 * GK;
    const float* __restrict__ row1 = g_pooled + (size_t)r1 * GK;
    __nv_bfloat16 bb[8], ss[8];
    bsplit(row0[k0],     bb[0], ss[0]);
    bsplit(row0[k0 + 1], bb[1], ss[1]);
    bsplit(row1[k0],     bb[2], ss[2]);
    bsplit(row1[k0 + 1], bb[3], ss[3]);
    bsplit(row0[k0 + 8], bb[4], ss[4]);
    bsplit(row0[k0 + 9], bb[5], ss[5]);
    bsplit(row1[k0 + 8], bb[6], ss[6]);
    bsplit(row1[k0 + 9], bb[7], ss[7]);
    int idx = (k16 * MTC + mt) * 32 + t;
    g_afb[idx] = make_uint4(packb(bb[0], bb[1]), packb(bb[2], bb[3]),
                            packb(bb[4], bb[5]), packb(bb[6], bb[7]));
    g_afs[idx] = make_uint4(packb(ss[0], ss[1]), packb(ss[2], ss[3]),
                            packb(ss[4], ss[5]), packb(ss[6], ss[7]));
}

// ---------------------------------------------------------------------------
// GEMM (3xBF16 m16n8k16): grid (7, 12, 6) = 504 blocks, 128 thr = 4 warps.
// Block tile 64m x 64n; warp tile 32m x 32n (2 mt x 4 nt, 24 mma/stage).
// 4-deep cp.async pipeline + REGISTER double-buffered fragments: stage st+1's
// LDS issues before stage st's mma, hiding LDS latency + barrier skew under
// the mma chain. Epilogue: red.global.add into out (bias pre-written).
// ---------------------------------------------------------------------------
__global__ __launch_bounds__(GEMM_THREADS) void gemm_kernel(float* __restrict__ out) {
    __shared__ uint4 sA[4][2][128];   // [buf][big/sm][mt_local*32+t] 16KB
    __shared__ uint2 sB[4][2][256];   // [buf][big/sm][nt_local*32+t] 16KB

    const int mb4 = blockIdx.x * 4;        // mtile base (0..24)
    const int nb8 = blockIdx.y * 8;        // ntile base
    const int z = blockIdx.z;
    const int k16z = z * K16_PER_Z;

    const int tid = threadIdx.x;
    const int lane = tid & 31;
    const int wid = tid >> 5;
    const int mwarp = wid >> 1;            // 0..1
    const int nwarp = wid & 1;             // 0..1

    auto load_stage = [&](int st) {
        if (st < K16_PER_Z) {
            const int buf = st & 3;
            const int k16g = k16z + st;
            const uint4* srcAb = g_afb + ((size_t)k16g * MTC + mb4) * 32;
            const uint4* srcAs = g_afs + ((size_t)k16g * MTC + mb4) * 32;
            const uint4* srcBb = (const uint4*)(g_bfb + ((size_t)k16g * NT + nb8) * 32);
            const uint4* srcBs = (const uint4*)(g_bfs + ((size_t)k16g * NT + nb8) * 32);
            cp_async16((unsigned int)__cvta_generic_to_shared(&sA[buf][0][tid]), srcAb + tid);
            cp_async16((unsigned int)__cvta_generic_to_shared(&sA[buf][1][tid]), srcAs + tid);
            cp_async16((unsigned int)__cvta_generic_to_shared(&sB[buf][0][2 * tid]), srcBb + tid);
            cp_async16((unsigned int)__cvta_generic_to_shared(&sB[buf][1][2 * tid]), srcBs + tid);
        }
        cp_commit();
    };

    uint4 abR[2][2], asR[2][2];
    uint2 bbR[2][4], bsR[2][4];
    auto load_frags = [&](int pp, int buf) {
#pragma unroll
        for (int i = 0; i < 2; ++i) {
            int mtl = mwarp * 2 + i;
            abR[pp][i] = sA[buf][0][mtl * 32 + lane];
            asR[pp][i] = sA[buf][1][mtl * 32 + lane];
        }
#pragma unroll
        for (int j = 0; j < 4; ++j) {
            int ntl = nwarp * 4 + j;
            bbR[pp][j] = sB[buf][0][ntl * 32 + lane];
            bsR[pp][j] = sB[buf][1][ntl * 32 + lane];
        }
    };

    float4 acc[2][4];
#pragma unroll
    for (int i = 0; i < 2; ++i)
#pragma unroll
        for (int j = 0; j < 4; ++j) acc[i][j] = make_float4(0.f, 0.f, 0.f, 0.f);

    load_stage(0);
    load_stage(1);
    load_stage(2);

    cp_wait<2>();
    __syncthreads();
    load_frags(0, 0);

#pragma unroll
    for (int st = 0; st < K16_PER_Z; ++st) {
        load_stage(st + 3);
        if (st + 1 < K16_PER_Z) {
            cp_wait<2>();          // groups <= st+1 complete
            __syncthreads();       // all warps past their frag-reads of buf st-1
            load_frags((st + 1) & 1, (st + 1) & 3);
        }
        const int pp = st & 1;
#pragma unroll
        for (int i = 0; i < 2; ++i)
#pragma unroll
            for (int j = 0; j < 4; ++j) {
                mma_bf16(acc[i][j], abR[pp][i], bbR[pp][j]);    // big*big
                mma_bf16(acc[i][j], abR[pp][i], bsR[pp][j]);    // big*small
                mma_bf16(acc[i][j], asR[pp][i], bbR[pp][j]);    // small*big
            }
    }

    // epilogue: atomic accumulate into out (bias already there)
    const int g = lane >> 2;
    const int c2 = (lane & 3) * 2;
#pragma unroll
    for (int i = 0; i < 2; ++i) {
        const int mtile = mb4 + mwarp * 2 + i;
        if (mtile < MTV) {                 // rows >= 400 are padding
            const int m0 = mtile * 16 + g;
#pragma unroll
            for (int j = 0; j < 4; ++j) {
                int n0 = (nb8 + nwarp * 4 + j) * 8 + c2;
                float* p0 = &out[(size_t)m0 * GN + n0];
                float* p1 = &out[(size_t)(m0 + 8) * GN + n0];
                redAdd(p0 + 0, acc[i][j].x);
                redAdd(p0 + 1, acc[i][j].y);
                redAdd(p1 + 0, acc[i][j].z);
                redAdd(p1 + 1, acc[i][j].w);
            }
        }
    }
}

// ---------------------------------------------------------------------------
extern "C" void kernel_launch(void* const* d_in, const int* in_sizes, int n_in,
                              void* d_out, int out_size) {
    const float* wf  = (const float*)d_in[0];   // [4,8192,768] f32
    const int*   ids = (const int*)d_in[1];     // [4,8192] i32
    const float* W2  = (const float*)d_in[2];   // [768,768] f32
    const float* b2  = (const float*)d_in[3];   // [768] f32
    float* out = (float*)d_out;                 // [4,100,768] f32

    init_kernel<<<INITP_BLOCKS, 256>>>(ids);
    pool_kernel<<<CVB_BLOCKS + POOL_BLOCKS, PBLK>>>(wf, ids, W2);
    convertA_kernel<<<CVA_BLOCKS + BIAS_BLOCKS, 256>>>(b2, out);
    gemm_kernel<<<dim3(7, GN / 64, SPLITK), GEMM_THREADS>>>(out);
}

// round 17
// speedup vs baseline: 1.2000x; 1.0570x over previous
#include <cuda_runtime.h>
#include <cuda_fp16.h>
#include <math_constants.h>
#include <cstdint>

// Problem constants
#define BB 4
#define LL 8192
#define DD 768
#define MAXS 100
#define GM (BB*MAXS)   // 400
#define M2 512         // padded M storage (rows 400-511 zero)
#define GN DD          // 768
#define GK DD          // 768
#define NK16 (GK/16)   // 48
#define MTC 28         // computed m-tiles (448 rows >= 400)
#define MTV 25         // valid m-tiles (400 rows)
#define NT (GN/8)      // 96 n-tiles

// pool config
#define TCH 32
#define PBLK 192
#define POOL_BLOCKS ((LL/TCH)*BB)        // 1024

// convert sizes
#define A16 (NK16 * MTC * 32)   // 43008
#define B16 (NK16 * NT * 32)    // 147456
#define CVB_BLOCKS (B16 / PBLK) // 768
#define CVA_BLOCKS (A16 / 256)  // 168
#define BIAS_BLOCKS 300         // out = bias (76800 float4)

// gemm config
#define SPLITK 6
#define K16_PER_Z (NK16/SPLITK) // 8 stages per block
#define GEMM_THREADS 128

#define INITP_BLOCKS 384        // g_pooled init (98304 float4)

// Scratch (device globals; allocation is forbidden)
__device__ float g_pooled[M2 * GK];        // [512][768] pooled, m-major
__device__ uint4 g_afb[A16];               // A frags big (fp16)  [k16][mt][t]
__device__ uint4 g_afs[A16];               // A frags small (fp16)
__device__ uint2 g_bfb[B16];               // B frags big (fp16)  [k16][nt][t]

// ---------------------------------------------------------------------------
// helpers
// ---------------------------------------------------------------------------
__device__ __forceinline__ void atomMaxF(float* a, float v) {
    if (v >= 0.0f) atomicMax((int*)a, __float_as_int(v));
    else           atomicMin((unsigned int*)a, __float_as_uint(v));
}
__device__ __forceinline__ void cp_async16(unsigned int smem, const void* gmem) {
    asm volatile("cp.async.cg.shared.global [%0], [%1], 16;\n" :: "r"(smem), "l"(gmem));
}
__device__ __forceinline__ void cp_commit() {
    asm volatile("cp.async.commit_group;\n");
}
template <int N>
__device__ __forceinline__ void cp_wait() {
    asm volatile("cp.async.wait_group %0;\n" :: "n"(N));
}
// split x into fp16 big + fp16 small (|small| <~ 2^-12 |x|); guard inf
__device__ __forceinline__ void hsplit(float x, __half& b, __half& s) {
    b = __float2half_rn(x);
    float r = isinf(x) ? 0.0f : x - __half2float(b);
    s = __float2half_rn(r);
}
__device__ __forceinline__ unsigned packh(__half lo, __half hi) {
    __half2 v; v.x = lo; v.y = hi;
    return *reinterpret_cast<unsigned*>(&v);
}
__device__ __forceinline__ void mma_f16(float4& d, uint4 a, uint2 b) {
    asm("mma.sync.aligned.m16n8k16.row.col.f32.f16.f16.f32 "
        "{%0,%1,%2,%3}, {%4,%5,%6,%7}, {%8,%9}, {%0,%1,%2,%3};"
        : "+f"(d.x), "+f"(d.y), "+f"(d.z), "+f"(d.w)
        : "r"(a.x), "r"(a.y), "r"(a.z), "r"(a.w), "r"(b.x), "r"(b.y));
}
__device__ __forceinline__ void redAdd(float* a, float v) {
    asm volatile("red.global.add.f32 [%0], %1;" :: "l"(a), "f"(v) : "memory");
}

// ---------------------------------------------------------------------------
// Init: g_pooled rows <400: -inf on valid slots else 0; rows 400-511: 0.
// ---------------------------------------------------------------------------
__global__ __launch_bounds__(256) void init_kernel(const int* __restrict__ ids) {
    int i4 = blockIdx.x * 256 + threadIdx.x;       // 0..98303
    int m = (i4 * 4) / DD;
    float val = 0.0f;
    if (m < GM) {
        int b = m / MAXS;
        int s = m - b * MAXS;
        int bbmax = __ldg(&ids[b * LL + LL - 1]);
        val = (s < bbmax) ? -CUDART_INF_F : 0.0f;
    }
    ((float4*)g_pooled)[i4] = make_float4(val, val, val, val);
}

// ---------------------------------------------------------------------------
// Pool + convert-B fused (independent jobs, overlap in one launch).
// convert-B: W2 -> fp16 BIG fragments only (2-product split needs no B-small).
// ---------------------------------------------------------------------------
__global__ __launch_bounds__(PBLK) void pool_kernel(const float* __restrict__ wf,
                                                    const int* __restrict__ ids,
                                                    const float* __restrict__ W2) {
    __shared__ int sid[TCH];
    const int tid = threadIdx.x;

    if (blockIdx.x < CVB_BLOCKS) {
        int j = blockIdx.x * PBLK + tid;           // 0..B16-1
        int t  = j & 31;
        int nt = (j >> 5) % NT;
        int k16 = j / (NT * 32);
        int g = t >> 2, c = (t & 3) * 2;
        int n  = nt * 8 + g;
        int k0 = k16 * 16 + c;
        const float* __restrict__ row = W2 + (size_t)n * GK;
        __half b00 = __float2half_rn(row[k0]);
        __half b01 = __float2half_rn(row[k0 + 1]);
        __half b10 = __float2half_rn(row[k0 + 8]);
        __half b11 = __float2half_rn(row[k0 + 9]);
        g_bfb[j] = make_uint2(packh(b00, b01), packh(b10, b11));
        return;
    }

    const int pb = blockIdx.x - CVB_BLOCKS;
    const int b = pb >> 8;                   // 256 chunks per batch
    const int c0 = (pb & 255) * TCH;
    if (tid < TCH) sid[tid] = ids[b * LL + c0 + tid];
    __syncthreads();

    const float4* __restrict__ base =
        (const float4*)(wf + ((size_t)b * LL + c0) * DD) + tid;

    float4 run = make_float4(-CUDART_INF_F, -CUDART_INF_F, -CUDART_INF_F, -CUDART_INF_F);
    int cur = -1;
    const int d0 = tid * 4;

#pragma unroll
    for (int t0 = 0; t0 < TCH; t0 += 8) {
        float4 v[8];
#pragma unroll
        for (int j = 0; j < 8; ++j)
            v[j] = __ldcs(base + (size_t)(t0 + j) * (DD / 4));
#pragma unroll
        for (int j = 0; j < 8; ++j) {
            int id = sid[t0 + j];
            if (id != cur) {
                if (cur > 0) {
                    float* p = g_pooled + (size_t)(b * MAXS + cur - 1) * DD + d0;
                    atomMaxF(p + 0, run.x);
                    atomMaxF(p + 1, run.y);
                    atomMaxF(p + 2, run.z);
                    atomMaxF(p + 3, run.w);
                }
                cur = id;
                run = make_float4(-CUDART_INF_F, -CUDART_INF_F, -CUDART_INF_F, -CUDART_INF_F);
            }
            if (id > 0) {
                run.x = fmaxf(run.x, v[j].x);
                run.y = fmaxf(run.y, v[j].y);
                run.z = fmaxf(run.z, v[j].z);
                run.w = fmaxf(run.w, v[j].w);
            }
        }
    }
    if (cur > 0) {
        float* p = g_pooled + (size_t)(b * MAXS + cur - 1) * DD + d0;
        atomMaxF(p + 0, run.x);
        atomMaxF(p + 1, run.y);
        atomMaxF(p + 2, run.z);
        atomMaxF(p + 3, run.w);
    }
}

// ---------------------------------------------------------------------------
// Convert-A + bias-prewrite fused.
// A gets BOTH fp16 big and small fragments (m16n8k16 A layout).
// ---------------------------------------------------------------------------
__global__ __launch_bounds__(256) void convertA_kernel(const float* __restrict__ b2,
                                                       float* __restrict__ out) {
    if (blockIdx.x >= CVA_BLOCKS) {
        int i4 = (blockIdx.x - CVA_BLOCKS) * 256 + threadIdx.x;  // 0..76799
        ((float4*)out)[i4] = ((const float4*)b2)[i4 % (GN / 4)];
        return;
    }
    int i = blockIdx.x * 256 + threadIdx.x;        // 0..A16-1 (exact)
    int t  = i & 31;
    int rest = i >> 5;
    int mt = rest % MTC;
    int k16 = rest / MTC;
    int g = t >> 2, c = (t & 3) * 2;
    int r0 = mt * 16 + g, r1 = r0 + 8;
    int k0 = k16 * 16 + c;
    const float* __restrict__ row0 = g_pooled + (size_t)r0 * GK;
    const float* __restrict__ row1 = g_pooled + (size_t)r1 * GK;
    __half bb[8], ss[8];
    hsplit(row0[k0],     bb[0], ss[0]);
    hsplit(row0[k0 + 1], bb[1], ss[1]);
    hsplit(row1[k0],     bb[2], ss[2]);
    hsplit(row1[k0 + 1], bb[3], ss[3]);
    hsplit(row0[k0 + 8], bb[4], ss[4]);
    hsplit(row0[k0 + 9], bb[5], ss[5]);
    hsplit(row1[k0 + 8], bb[6], ss[6]);
    hsplit(row1[k0 + 9], bb[7], ss[7]);
    int idx = (k16 * MTC + mt) * 32 + t;
    g_afb[idx] = make_uint4(packh(bb[0], bb[1]), packh(bb[2], bb[3]),
                            packh(bb[4], bb[5]), packh(bb[6], bb[7]));
    g_afs[idx] = make_uint4(packh(ss[0], ss[1]), packh(ss[2], ss[3]),
                            packh(ss[4], ss[5]), packh(ss[6], ss[7]));
}

// ---------------------------------------------------------------------------
// GEMM (2xFP16 m16n8k16): out += (Ab + As) @ Bb^T, per k-chunk z.
// grid (7, 12, 6) = 504 blocks, 128 thr = 4 warps (2m x 2n).
// Block tile 64m x 64n; warp tile 32m x 32n (2 mt x 4 nt, 16 mma/stage).
// 4-deep cp.async pipeline + register double-buffered fragments.
// Epilogue: red.global.add into out (bias pre-written).
// ---------------------------------------------------------------------------
__global__ __launch_bounds__(GEMM_THREADS) void gemm_kernel(float* __restrict__ out) {
    __shared__ uint4 sA[4][2][128];   // [buf][big/sm][mt_local*32+t] 16KB
    __shared__ uint2 sB[4][256];      // [buf][nt_local*32+t]          8KB

    const int mb4 = blockIdx.x * 4;        // mtile base (0..24)
    const int nb8 = blockIdx.y * 8;        // ntile base
    const int z = blockIdx.z;
    const int k16z = z * K16_PER_Z;

    const int tid = threadIdx.x;
    const int lane = tid & 31;
    const int wid = tid >> 5;
    const int mwarp = wid >> 1;            // 0..1
    const int nwarp = wid & 1;             // 0..1

    auto load_stage = [&](int st) {
        if (st < K16_PER_Z) {
            const int buf = st & 3;
            const int k16g = k16z + st;
            const uint4* srcAb = g_afb + ((size_t)k16g * MTC + mb4) * 32;
            const uint4* srcAs = g_afs + ((size_t)k16g * MTC + mb4) * 32;
            const uint4* srcBb = (const uint4*)(g_bfb + ((size_t)k16g * NT + nb8) * 32);
            cp_async16((unsigned int)__cvta_generic_to_shared(&sA[buf][0][tid]), srcAb + tid);
            cp_async16((unsigned int)__cvta_generic_to_shared(&sA[buf][1][tid]), srcAs + tid);
            cp_async16((unsigned int)__cvta_generic_to_shared(&sB[buf][2 * tid]), srcBb + tid);
        }
        cp_commit();
    };

    uint4 abR[2][2], asR[2][2];
    uint2 bbR[2][4];
    auto load_frags = [&](int pp, int buf) {
#pragma unroll
        for (int i = 0; i < 2; ++i) {
            int mtl = mwarp * 2 + i;
            abR[pp][i] = sA[buf][0][mtl * 32 + lane];
            asR[pp][i] = sA[buf][1][mtl * 32 + lane];
        }
#pragma unroll
        for (int j = 0; j < 4; ++j) {
            int ntl = nwarp * 4 + j;
            bbR[pp][j] = sB[buf][ntl * 32 + lane];
        }
    };

    float4 acc[2][4];
#pragma unroll
    for (int i = 0; i < 2; ++i)
#pragma unroll
        for (int j = 0; j < 4; ++j) acc[i][j] = make_float4(0.f, 0.f, 0.f, 0.f);

    load_stage(0);
    load_stage(1);
    load_stage(2);

    cp_wait<2>();
    __syncthreads();
    load_frags(0, 0);

#pragma unroll
    for (int st = 0; st < K16_PER_Z; ++st) {
        load_stage(st + 3);
        if (st + 1 < K16_PER_Z) {
            cp_wait<2>();          // groups <= st+1 complete
            __syncthreads();       // all warps past their frag-reads of buf st-1
            load_frags((st + 1) & 1, (st + 1) & 3);
        }
        const int pp = st & 1;
#pragma unroll
        for (int i = 0; i < 2; ++i)
#pragma unroll
            for (int j = 0; j < 4; ++j) {
                mma_f16(acc[i][j], abR[pp][i], bbR[pp][j]);    // big*big
                mma_f16(acc[i][j], asR[pp][i], bbR[pp][j]);    // small*big
            }
    }

    // epilogue: atomic accumulate into out (bias already there)
    const int g = lane >> 2;
    const int c2 = (lane & 3) * 2;
#pragma unroll
    for (int i = 0; i < 2; ++i) {
        const int mtile = mb4 + mwarp * 2 + i;
        if (mtile < MTV) {                 // rows >= 400 are padding
            const int m0 = mtile * 16 + g;
#pragma unroll
            for (int j = 0; j < 4; ++j) {
                int n0 = (nb8 + nwarp * 4 + j) * 8 + c2;
                float* p0 = &out[(size_t)m0 * GN + n0];
                float* p1 = &out[(size_t)(m0 + 8) * GN + n0];
                redAdd(p0 + 0, acc[i][j].x);
                redAdd(p0 + 1, acc[i][j].y);
                redAdd(p1 + 0, acc[i][j].z);
                redAdd(p1 + 1, acc[i][j].w);
            }
        }
    }
}

// ---------------------------------------------------------------------------
extern "C" void kernel_launch(void* const* d_in, const int* in_sizes, int n_in,
                              void* d_out, int out_size) {
    const float* wf  = (const float*)d_in[0];   // [4,8192,768] f32
    const int*   ids = (const int*)d_in[1];     // [4,8192] i32
    const float* W2  = (const float*)d_in[2];   // [768,768] f32
    const float* b2  = (const float*)d_in[3];   // [768] f32
    float* out = (float*)d_out;                 // [4,100,768] f32

    init_kernel<<<INITP_BLOCKS, 256>>>(ids);
    pool_kernel<<<CVB_BLOCKS + POOL_BLOCKS, PBLK>>>(wf, ids, W2);
    convertA_kernel<<<CVA_BLOCKS + BIAS_BLOCKS, 256>>>(b2, out);
    gemm_kernel<<<dim3(7, GN / 64, SPLITK), GEMM_THREADS>>>(out);
}